// round 8
// baseline (speedup 1.0000x reference)
#include <cuda_runtime.h>
#include <cuda.h>
#include <cuda_fp16.h>
#include <cstdint>

// ---------------- problem constants ----------------
#define N_NODES 10000
#define IN_DIM  128
#define OUT_DIM 64
#define M_TILE  80                       // 125 CTAs exactly, 1 per SM
#define K_CHUNK 64
#define NUM_ITERS ((N_NODES + K_CHUNK - 1) / K_CHUNK)   // 157
#define STAGES  5
#define NTHREADS 256                     // 3 MMA + 4 converter warps + 1 producer

#define RAW_BYTES (M_TILE * K_CHUNK * 4)      // 20480 int32 adj tile
#define A_BYTES   (M_TILE * K_CHUNK * 2)      // 10240 fp16 SW128 A tile
#define B_BYTES   (OUT_DIM * K_CHUNK * 2)     // 8192  fp16 SW128 B tile
#define STAGE_BYTES (RAW_BYTES + A_BYTES + B_BYTES)   // 38912 (38*1024)
#define SMEM_MAIN (STAGES * STAGE_BYTES)              // 194560
#define SMEM_TOTAL (SMEM_MAIN + 256 + 1024)

// ---------------- device scratch (no allocs allowed) ----------------
__device__ __align__(1024) __half g_WhT[OUT_DIM * N_NODES];

// ---------------- PTX helpers (plain sm_103-safe) ----------------
__device__ __forceinline__ uint32_t smem_u32(const void* p) {
    uint32_t a;
    asm("{ .reg .u64 t; cvta.to.shared.u64 t, %1; cvt.u32.u64 %0, t; }" : "=r"(a) : "l"(p));
    return a;
}
#define MBAR_INIT(a,c)  asm volatile("mbarrier.init.shared.b64 [%0], %1;" :: "r"(a), "r"(c) : "memory")
#define MBAR_ARRIVE(a)  asm volatile("mbarrier.arrive.shared.b64 _, [%0];" :: "r"(a) : "memory")
#define MBAR_EXPECT_TX(a,b) asm volatile("mbarrier.arrive.expect_tx.shared.b64 _, [%0], %1;" :: "r"(a), "r"(b) : "memory")

#define MBAR_WAIT(mbar_addr, phase_parity) do {                                \
    uint32_t _mbar = (uint32_t)(mbar_addr);                                    \
    uint32_t _par  = (uint32_t)(phase_parity);                                 \
    uint32_t _done_;                                                           \
    asm volatile("{\n\t.reg .pred p;\n\t"                                      \
        "mbarrier.try_wait.parity.acquire.cta.shared::cta.b64 p, [%1], %2;\n\t"\
        "selp.b32 %0, 1, 0, p;\n\t}"                                           \
        : "=r"(_done_) : "r"(_mbar), "r"(_par) : "memory");                    \
    if (!_done_) {                                                             \
        asm volatile("{\n\t.reg .pred P1;\n\t"                                 \
            "WL_%=:\n\t"                                                       \
            "mbarrier.try_wait.parity.acquire.cta.shared::cta.b64 P1, [%0], %1, 0x989680;\n\t" \
            "@P1 bra.uni WD_%=;\n\t"                                           \
            "bra.uni WL_%=;\n\t"                                               \
            "WD_%=:\n\t}"                                                      \
            :: "r"(_mbar), "r"(_par) : "memory");                              \
    }                                                                          \
} while (0)

#define TMA_LOAD_2D(dst, map, x, y, mbar)                                      \
    asm volatile(                                                              \
        "cp.async.bulk.tensor.2d.shared::cta.global.tile.mbarrier::complete_tx::bytes " \
        "[%0], [%1, {%2, %3}], [%4];"                                          \
        :: "r"((uint32_t)(dst)), "l"(map), "r"((int)(x)), "r"((int)(y)),       \
           "r"((uint32_t)(mbar)) : "memory")

#define LDMATRIX_X4(r0,r1,r2,r3,addr) \
    asm volatile("ldmatrix.sync.aligned.m8n8.x4.shared.b16 {%0,%1,%2,%3}, [%4];" \
        : "=r"(r0),"=r"(r1),"=r"(r2),"=r"(r3) : "r"(addr))

#define HMMA_16816(C, a0,a1,a2,a3, b0,b1) \
    asm volatile("mma.sync.aligned.m16n8k16.row.col.f32.f16.f16.f32 " \
        "{%0,%1,%2,%3}, {%4,%5,%6,%7}, {%8,%9}, {%0,%1,%2,%3};" \
        : "+f"((C)[0]),"+f"((C)[1]),"+f"((C)[2]),"+f"((C)[3]) \
        : "r"(a0),"r"(a1),"r"(a2),"r"(a3),"r"(b0),"r"(b1))

// ---------------- kernel 1: WhT = (h@W)^T in fp16 (80 nodes / block) ----------------
__global__ void __launch_bounds__(256) prep_kernel(
    const float* __restrict__ h, const float* __restrict__ W)
{
    __shared__ float Ws[IN_DIM * OUT_DIM];      // 32KB [k][col]
    __shared__ float hsm[M_TILE * IN_DIM];      // 40KB [node][k]
    const int tid = threadIdx.x;
    const int node0 = blockIdx.x * M_TILE;

    const float4* W4 = (const float4*)W;
    float4* Ws4 = (float4*)Ws;
#pragma unroll
    for (int i = 0; i < 8; i++) Ws4[tid + i * 256] = W4[tid + i * 256];
    const float4* h4 = (const float4*)(h + (size_t)node0 * IN_DIM);
    float4* hs4 = (float4*)hsm;
#pragma unroll
    for (int i = 0; i < 10; i++) hs4[tid + i * 256] = h4[tid + i * 256];
    __syncthreads();

    const int c4 = tid & 15;                    // cols 4*c4 .. 4*c4+3
    const int ng = tid >> 4;                    // nodes ng*5 .. ng*5+4
    float acc[5][4];
#pragma unroll
    for (int n = 0; n < 5; n++)
#pragma unroll
        for (int c = 0; c < 4; c++) acc[n][c] = 0.f;

#pragma unroll 2
    for (int k4 = 0; k4 < 32; k4++) {
        float4 hv[5];
#pragma unroll
        for (int n = 0; n < 5; n++)
            hv[n] = *(const float4*)&hsm[(ng * 5 + n) * IN_DIM + k4 * 4];
#pragma unroll
        for (int kk = 0; kk < 4; kk++) {
            float4 wv = *(const float4*)&Ws[(k4 * 4 + kk) * OUT_DIM + c4 * 4];
#pragma unroll
            for (int n = 0; n < 5; n++) {
                float hx = (&hv[n].x)[kk];
                acc[n][0] += hx * wv.x;
                acc[n][1] += hx * wv.y;
                acc[n][2] += hx * wv.z;
                acc[n][3] += hx * wv.w;
            }
        }
    }
#pragma unroll
    for (int n = 0; n < 5; n++) {
        int node = node0 + ng * 5 + n;
#pragma unroll
        for (int c = 0; c < 4; c++)
            g_WhT[(size_t)(c4 * 4 + c) * N_NODES + node] = __float2half(acc[n][c]);
    }
}

// ---------------- kernel 2: masked mean via HMMA pipeline ----------------
__global__ void __launch_bounds__(NTHREADS, 1) gat_main_kernel(
    const __grid_constant__ CUtensorMap tma_adj,
    const __grid_constant__ CUtensorMap tma_b,
    float* __restrict__ out)
{
    extern __shared__ char smem_raw[];
    const int tid = threadIdx.x;
    const int wid = tid >> 5;
    const int lid = tid & 31;

    uint32_t sb0 = smem_u32(smem_raw);
    uint32_t sbase = (sb0 + 1023u) & ~1023u;
    char* smem = smem_raw + (sbase - sb0);
    const uint32_t mb = sbase + SMEM_MAIN;
    // mbar layout: empty[5] @0 (cnt 3), full_raw[5] @40 (TMA tx), full_conv[5] @80 (cnt 128)

    __shared__ int sdeg[M_TILE];

    if (tid == 0) {
        for (int s = 0; s < STAGES; s++) {
            MBAR_INIT(mb + s * 8, 3);           // empty: 3 MMA-warp arrivals
            MBAR_INIT(mb + 40 + s * 8, 1);      // full_raw: TMA tx
            MBAR_INIT(mb + 80 + s * 8, 128);    // full_conv: 128 conv threads
        }
    }
    __syncthreads();

    const int row0 = blockIdx.x * M_TILE;

    if (tid == 224) {
        // ---------------- TMA producer ----------------
        int s = 0, ph = 1;
        for (int it = 0; it < NUM_ITERS; it++) {
            MBAR_WAIT(mb + s * 8, ph);                       // wait stage empty
            uint32_t dst = sbase + s * STAGE_BYTES;
            uint32_t fr = mb + 40 + s * 8;
            MBAR_EXPECT_TX(fr, RAW_BYTES + B_BYTES);
            TMA_LOAD_2D(dst, &tma_adj, it * K_CHUNK, row0, fr);
            TMA_LOAD_2D(dst + RAW_BYTES + A_BYTES, &tma_b, it * K_CHUNK, 0, fr);
            if (++s == STAGES) { s = 0; ph ^= 1; }
        }
    } else if (wid >= 3 && wid < 7) {
        // ---------------- converters: int32 adj -> fp16 A (SW128) + degree ----------------
        const int ct = tid - 96;                             // 0..127
        int dacc[10];
#pragma unroll
        for (int g = 0; g < 10; g++) dacc[g] = 0;
        int s = 0, ph = 0;
        for (int it = 0; it < NUM_ITERS; it++) {
            MBAR_WAIT(mb + 40 + s * 8, ph);                  // wait TMA data
            const uint4* rawv = (const uint4*)(smem + s * STAGE_BYTES);
            char* aT = smem + s * STAGE_BYTES + RAW_BYTES;
#pragma unroll
            for (int g = 0; g < 10; g++) {
                int idx = g * 128 + ct;                      // linear: conflict-free LDS.128
                uint4 v = rawv[idx];
                dacc[g] += (int)(v.x + v.y + v.z + v.w);
                uint32_t u0 = v.x * 0x3C00u + v.y * 0x3C000000u;  // 2x fp16 {1.0,0.0}
                uint32_t u1 = v.z * 0x3C00u + v.w * 0x3C000000u;
                uint32_t off = (uint32_t)((idx >> 4) * 128 + (idx & 15) * 8);
                off ^= (off >> 3) & 0x70;                    // SW128 swizzle
                *(uint2*)(aT + off) = make_uint2(u0, u1);
            }
            MBAR_ARRIVE(mb + 80 + s * 8);                    // release A tile
            if (++s == STAGES) { s = 0; ph ^= 1; }
        }
        // degree reduce: row = g*8 + (ct>>4); partials across 16 lanes
#pragma unroll
        for (int g = 0; g < 10; g++) {
            int d = dacc[g];
            d += __shfl_xor_sync(0xffffffffu, d, 1);
            d += __shfl_xor_sync(0xffffffffu, d, 2);
            d += __shfl_xor_sync(0xffffffffu, d, 4);
            d += __shfl_xor_sync(0xffffffffu, d, 8);
            if ((ct & 15) == 0) sdeg[g * 8 + (ct >> 4)] = d;
        }
    } else if (wid < 3) {
        // ---------------- MMA warps: warp 0,1 -> 32 rows; warp 2 -> 16 rows --------
        const int mcnt = (wid == 2) ? 1 : 2;
        const int mbase = wid * 32;
        float acc[2][8][4];
#pragma unroll
        for (int m = 0; m < 2; m++)
#pragma unroll
            for (int t = 0; t < 8; t++)
#pragma unroll
                for (int p = 0; p < 4; p++) acc[m][t][p] = 0.f;
        const int sub = lid >> 3, rl = lid & 7;
        int s = 0, ph = 0;
        for (int it = 0; it < NUM_ITERS; it++) {
            MBAR_WAIT(mb + 80 + s * 8, ph);                  // A converted (implies B too)
            uint32_t aBase = sbase + s * STAGE_BYTES + RAW_BYTES;
            uint32_t bBase = aBase + A_BYTES;
#pragma unroll
            for (int kt = 0; kt < 4; kt++) {
                // A fragments for this warp's m-tiles
                uint32_t a[2][4];
#pragma unroll
                for (int mt = 0; mt < 2; mt++) {
                    if (mt < mcnt) {
                        int row = mbase + mt * 16 + (sub & 1) * 8 + rl;
                        uint32_t off = (uint32_t)(row * 128 + kt * 32 + (sub >> 1) * 16);
                        off ^= (off >> 3) & 0x70;
                        LDMATRIX_X4(a[mt][0], a[mt][1], a[mt][2], a[mt][3], aBase + off);
                    }
                }
                // B fragments loaded ONCE, reused across m-tiles
#pragma unroll
                for (int ng = 0; ng < 4; ng++) {
                    uint32_t b0, b1, b2, b3;
                    int nrow = ng * 16 + (sub >> 1) * 8 + rl;
                    uint32_t off = (uint32_t)(nrow * 128 + kt * 32 + (sub & 1) * 16);
                    off ^= (off >> 3) & 0x70;                // SW128 swizzle
                    LDMATRIX_X4(b0, b1, b2, b3, bBase + off);
                    HMMA_16816(acc[0][ng * 2],     a[0][0], a[0][1], a[0][2], a[0][3], b0, b1);
                    HMMA_16816(acc[0][ng * 2 + 1], a[0][0], a[0][1], a[0][2], a[0][3], b2, b3);
                    if (mcnt == 2) {
                        HMMA_16816(acc[1][ng * 2],     a[1][0], a[1][1], a[1][2], a[1][3], b0, b1);
                        HMMA_16816(acc[1][ng * 2 + 1], a[1][0], a[1][1], a[1][2], a[1][3], b2, b3);
                    }
                }
            }
            if (lid == 0) MBAR_ARRIVE(mb + s * 8);           // stage consumed
            if (++s == STAGES) { s = 0; ph ^= 1; }
        }

        __syncthreads();

        // ---------------- epilogue: divide by degree, store ----------------
        const int gg = lid >> 2, tg = lid & 3;
#pragma unroll
        for (int mt = 0; mt < 2; mt++) {
            if (mt < mcnt) {
                const int r0 = mbase + mt * 16 + gg, r1 = r0 + 8;
                float inv0 = 1.0f / (float)sdeg[r0];
                float inv1 = 1.0f / (float)sdeg[r1];
                float* o0 = out + (size_t)(row0 + r0) * OUT_DIM + tg * 2;
                float* o1 = out + (size_t)(row0 + r1) * OUT_DIM + tg * 2;
#pragma unroll
                for (int t = 0; t < 8; t++) {
                    *(float2*)(o0 + t * 8) = make_float2(acc[mt][t][0] * inv0,
                                                         acc[mt][t][1] * inv0);
                    *(float2*)(o1 + t * 8) = make_float2(acc[mt][t][2] * inv1,
                                                         acc[mt][t][3] * inv1);
                }
            }
        }
        return;
    }
    __syncthreads();   // converters + producer join the pre-epilogue barrier
}

// ---------------- host ----------------
typedef CUresult (*EncodeFn)(CUtensorMap*, CUtensorMapDataType, cuuint32_t, void*,
                             const cuuint64_t*, const cuuint64_t*, const cuuint32_t*,
                             const cuuint32_t*, CUtensorMapInterleave, CUtensorMapSwizzle,
                             CUtensorMapL2promotion, CUtensorMapFloatOOBfill);

static EncodeFn get_encode_fn() {
    void* fp = nullptr;
    cudaDriverEntryPointQueryResult qr;
#if CUDART_VERSION >= 12050
    cudaGetDriverEntryPointByVersion("cuTensorMapEncodeTiled", &fp, 12000,
                                     cudaEnableDefault, &qr);
#else
    cudaGetDriverEntryPoint("cuTensorMapEncodeTiled", &fp, cudaEnableDefault, &qr);
#endif
    return (EncodeFn)fp;
}

extern "C" void kernel_launch(void* const* d_in, const int* in_sizes, int n_in,
                              void* d_out, int out_size) {
    const float* h   = (const float*)d_in[0];
    void*        adj = (void*)d_in[1];           // int32 [10000,10000], values 0/1
    const float* W   = (const float*)d_in[2];
    float*       out = (float*)d_out;

    prep_kernel<<<N_NODES / M_TILE, 256>>>(h, W);

    EncodeFn enc = get_encode_fn();
    void* whtPtr = nullptr;
    cudaGetSymbolAddress(&whtPtr, g_WhT);

    CUtensorMap tmaAdj, tmaB;
    {   // adj: int32 [10000][10000], box [64,80], no swizzle
        cuuint64_t dims[2]    = {N_NODES, N_NODES};
        cuuint64_t strides[1] = {(cuuint64_t)N_NODES * 4};
        cuuint32_t box[2]     = {K_CHUNK, M_TILE};
        cuuint32_t es[2]      = {1, 1};
        enc(&tmaAdj, CU_TENSOR_MAP_DATA_TYPE_UINT32, 2, adj, dims, strides, box, es,
            CU_TENSOR_MAP_INTERLEAVE_NONE, CU_TENSOR_MAP_SWIZZLE_NONE,
            CU_TENSOR_MAP_L2_PROMOTION_L2_128B, CU_TENSOR_MAP_FLOAT_OOB_FILL_NONE);
    }
    {   // WhT: fp16 [64][10000], box [64,64], SW128 (row = 128B)
        cuuint64_t dims[2]    = {N_NODES, OUT_DIM};
        cuuint64_t strides[1] = {(cuuint64_t)N_NODES * 2};
        cuuint32_t box[2]     = {K_CHUNK, OUT_DIM};
        cuuint32_t es[2]      = {1, 1};
        enc(&tmaB, CU_TENSOR_MAP_DATA_TYPE_FLOAT16, 2, whtPtr, dims, strides, box, es,
            CU_TENSOR_MAP_INTERLEAVE_NONE, CU_TENSOR_MAP_SWIZZLE_128B,
            CU_TENSOR_MAP_L2_PROMOTION_L2_128B, CU_TENSOR_MAP_FLOAT_OOB_FILL_NONE);
    }

    cudaFuncSetAttribute(gat_main_kernel, cudaFuncAttributeMaxDynamicSharedMemorySize,
                         SMEM_TOTAL);
    int grid = N_NODES / M_TILE;   // 125: one CTA per SM, single balanced wave
    gat_main_kernel<<<grid, NTHREADS, SMEM_TOTAL>>>(tmaAdj, tmaB, out);

    (void)in_sizes; (void)n_in; (void)out_size;
}

// round 9
// speedup vs baseline: 1.2300x; 1.2300x over previous
#include <cuda_runtime.h>
#include <cuda.h>
#include <cuda_fp16.h>
#include <cstdint>

// ---------------- problem constants ----------------
#define N_NODES 10000
#define IN_DIM  128
#define OUT_DIM 64
#define M_TILE  80                       // 125 CTAs exactly, 1 per SM
#define K_CHUNK 64
#define NUM_ITERS ((N_NODES + K_CHUNK - 1) / K_CHUNK)   // 157
#define STAGES  5
#define NTHREADS 512                     // 10 MMA (K-split) + 5 conv + 1 producer

#define RAW_BYTES (M_TILE * K_CHUNK * 4)      // 20480 int32 adj tile
#define A_BYTES   (M_TILE * K_CHUNK * 2)      // 10240 fp16 SW128 A tile
#define B_BYTES   (OUT_DIM * K_CHUNK * 2)     // 8192  fp16 SW128 B tile
#define STAGE_BYTES (RAW_BYTES + A_BYTES + B_BYTES)   // 38912 (38*1024)
#define SMEM_MAIN (STAGES * STAGE_BYTES)              // 194560
#define SMEM_TOTAL (SMEM_MAIN + 256 + 1024)

#define RED_STRIDE 68                    // padded cols for partial-sum buffer

// ---------------- device scratch (no allocs allowed) ----------------
__device__ __align__(1024) __half g_WhT[OUT_DIM * N_NODES];

// ---------------- PTX helpers (plain sm_103-safe) ----------------
__device__ __forceinline__ uint32_t smem_u32(const void* p) {
    uint32_t a;
    asm("{ .reg .u64 t; cvta.to.shared.u64 t, %1; cvt.u32.u64 %0, t; }" : "=r"(a) : "l"(p));
    return a;
}
#define MBAR_INIT(a,c)  asm volatile("mbarrier.init.shared.b64 [%0], %1;" :: "r"(a), "r"(c) : "memory")
#define MBAR_ARRIVE(a)  asm volatile("mbarrier.arrive.shared.b64 _, [%0];" :: "r"(a) : "memory")
#define MBAR_EXPECT_TX(a,b) asm volatile("mbarrier.arrive.expect_tx.shared.b64 _, [%0], %1;" :: "r"(a), "r"(b) : "memory")

#define MBAR_WAIT(mbar_addr, phase_parity) do {                                \
    uint32_t _mbar = (uint32_t)(mbar_addr);                                    \
    uint32_t _par  = (uint32_t)(phase_parity);                                 \
    uint32_t _done_;                                                           \
    asm volatile("{\n\t.reg .pred p;\n\t"                                      \
        "mbarrier.try_wait.parity.acquire.cta.shared::cta.b64 p, [%1], %2;\n\t"\
        "selp.b32 %0, 1, 0, p;\n\t}"                                           \
        : "=r"(_done_) : "r"(_mbar), "r"(_par) : "memory");                    \
    if (!_done_) {                                                             \
        asm volatile("{\n\t.reg .pred P1;\n\t"                                 \
            "WL_%=:\n\t"                                                       \
            "mbarrier.try_wait.parity.acquire.cta.shared::cta.b64 P1, [%0], %1, 0x989680;\n\t" \
            "@P1 bra.uni WD_%=;\n\t"                                           \
            "bra.uni WL_%=;\n\t"                                               \
            "WD_%=:\n\t}"                                                      \
            :: "r"(_mbar), "r"(_par) : "memory");                              \
    }                                                                          \
} while (0)

#define TMA_LOAD_2D(dst, map, x, y, mbar)                                      \
    asm volatile(                                                              \
        "cp.async.bulk.tensor.2d.shared::cta.global.tile.mbarrier::complete_tx::bytes " \
        "[%0], [%1, {%2, %3}], [%4];"                                          \
        :: "r"((uint32_t)(dst)), "l"(map), "r"((int)(x)), "r"((int)(y)),       \
           "r"((uint32_t)(mbar)) : "memory")

#define LDMATRIX_X4(r0,r1,r2,r3,addr) \
    asm volatile("ldmatrix.sync.aligned.m8n8.x4.shared.b16 {%0,%1,%2,%3}, [%4];" \
        : "=r"(r0),"=r"(r1),"=r"(r2),"=r"(r3) : "r"(addr))

#define HMMA_16816(C, a0,a1,a2,a3, b0,b1) \
    asm volatile("mma.sync.aligned.m16n8k16.row.col.f32.f16.f16.f32 " \
        "{%0,%1,%2,%3}, {%4,%5,%6,%7}, {%8,%9}, {%0,%1,%2,%3};" \
        : "+f"((C)[0]),"+f"((C)[1]),"+f"((C)[2]),"+f"((C)[3]) \
        : "r"(a0),"r"(a1),"r"(a2),"r"(a3),"r"(b0),"r"(b1))

// ---------------- kernel 1: WhT = (h@W)^T in fp16 (80 nodes / block) ----------------
__global__ void __launch_bounds__(256) prep_kernel(
    const float* __restrict__ h, const float* __restrict__ W)
{
    __shared__ float Ws[IN_DIM * OUT_DIM];      // 32KB [k][col]
    __shared__ float hsm[M_TILE * IN_DIM];      // 40KB [node][k]
    const int tid = threadIdx.x;
    const int node0 = blockIdx.x * M_TILE;

    const float4* W4 = (const float4*)W;
    float4* Ws4 = (float4*)Ws;
#pragma unroll
    for (int i = 0; i < 8; i++) Ws4[tid + i * 256] = W4[tid + i * 256];
    const float4* h4 = (const float4*)(h + (size_t)node0 * IN_DIM);
    float4* hs4 = (float4*)hsm;
#pragma unroll
    for (int i = 0; i < 10; i++) hs4[tid + i * 256] = h4[tid + i * 256];
    __syncthreads();

    const int c4 = tid & 15;                    // cols 4*c4 .. 4*c4+3
    const int ng = tid >> 4;                    // nodes ng*5 .. ng*5+4
    float acc[5][4];
#pragma unroll
    for (int n = 0; n < 5; n++)
#pragma unroll
        for (int c = 0; c < 4; c++) acc[n][c] = 0.f;

#pragma unroll 2
    for (int k4 = 0; k4 < 32; k4++) {
        float4 hv[5];
#pragma unroll
        for (int n = 0; n < 5; n++)
            hv[n] = *(const float4*)&hsm[(ng * 5 + n) * IN_DIM + k4 * 4];
#pragma unroll
        for (int kk = 0; kk < 4; kk++) {
            float4 wv = *(const float4*)&Ws[(k4 * 4 + kk) * OUT_DIM + c4 * 4];
#pragma unroll
            for (int n = 0; n < 5; n++) {
                float hx = (&hv[n].x)[kk];
                acc[n][0] += hx * wv.x;
                acc[n][1] += hx * wv.y;
                acc[n][2] += hx * wv.z;
                acc[n][3] += hx * wv.w;
            }
        }
    }
#pragma unroll
    for (int n = 0; n < 5; n++) {
        int node = node0 + ng * 5 + n;
#pragma unroll
        for (int c = 0; c < 4; c++)
            g_WhT[(size_t)(c4 * 4 + c) * N_NODES + node] = __float2half(acc[n][c]);
    }
}

// ---------------- kernel 2: masked mean via K-split HMMA pipeline ----------------
__global__ void __launch_bounds__(NTHREADS, 1) gat_main_kernel(
    const __grid_constant__ CUtensorMap tma_adj,
    const __grid_constant__ CUtensorMap tma_b,
    float* __restrict__ out)
{
    extern __shared__ char smem_raw[];
    const int tid = threadIdx.x;
    const int wid = tid >> 5;
    const int lid = tid & 31;

    uint32_t sb0 = smem_u32(smem_raw);
    uint32_t sbase = (sb0 + 1023u) & ~1023u;
    char* smem = smem_raw + (sbase - sb0);
    const uint32_t mb = sbase + SMEM_MAIN;
    // mbar layout: empty[5]@0 (cnt 10), full_raw[5]@40 (TMA tx), full_conv[5]@80 (cnt 160)

    __shared__ int sdeg[M_TILE];

    if (tid == 0) {
        for (int s = 0; s < STAGES; s++) {
            MBAR_INIT(mb + s * 8, 10);          // empty: 10 MMA-warp arrivals
            MBAR_INIT(mb + 40 + s * 8, 1);      // full_raw: TMA tx
            MBAR_INIT(mb + 80 + s * 8, 160);    // full_conv: 160 conv threads
        }
    }
    __syncthreads();

    const int row0 = blockIdx.x * M_TILE;
    float acc[8][4];
#pragma unroll
    for (int t = 0; t < 8; t++)
#pragma unroll
        for (int p = 0; p < 4; p++) acc[t][p] = 0.f;

    if (tid == 480) {
        // ---------------- TMA producer ----------------
        int s = 0, ph = 1;
        for (int it = 0; it < NUM_ITERS; it++) {
            MBAR_WAIT(mb + s * 8, ph);                       // wait stage empty
            uint32_t dst = sbase + s * STAGE_BYTES;
            uint32_t fr = mb + 40 + s * 8;
            MBAR_EXPECT_TX(fr, RAW_BYTES + B_BYTES);
            TMA_LOAD_2D(dst, &tma_adj, it * K_CHUNK, row0, fr);
            TMA_LOAD_2D(dst + RAW_BYTES + A_BYTES, &tma_b, it * K_CHUNK, 0, fr);
            if (++s == STAGES) { s = 0; ph ^= 1; }
        }
    } else if (wid >= 10 && wid < 15) {
        // ---------------- converters: int32 adj -> fp16 A (SW128) + degree ----------
        const int ct = tid - 320;                            // 0..159
        int dacc[8];
#pragma unroll
        for (int g = 0; g < 8; g++) dacc[g] = 0;
        int s = 0, ph = 0;
        for (int it = 0; it < NUM_ITERS; it++) {
            MBAR_WAIT(mb + 40 + s * 8, ph);                  // wait TMA data
            const uint4* rawv = (const uint4*)(smem + s * STAGE_BYTES);
            char* aT = smem + s * STAGE_BYTES + RAW_BYTES;
#pragma unroll
            for (int g = 0; g < 8; g++) {
                int idx = g * 160 + ct;                      // linear: conflict-free LDS.128
                uint4 v = rawv[idx];
                dacc[g] += (int)(v.x + v.y + v.z + v.w);
                uint32_t u0 = v.x * 0x3C00u + v.y * 0x3C000000u;  // 2x fp16 {1.0,0.0}
                uint32_t u1 = v.z * 0x3C00u + v.w * 0x3C000000u;
                uint32_t off = (uint32_t)((idx >> 4) * 128 + (idx & 15) * 8);
                off ^= (off >> 3) & 0x70;                    // SW128 swizzle
                *(uint2*)(aT + off) = make_uint2(u0, u1);
            }
            MBAR_ARRIVE(mb + 80 + s * 8);                    // release A tile
            if (++s == STAGES) { s = 0; ph ^= 1; }
        }
        // degree reduce: group g covers row g*10 + (ct>>4); 16 lanes share a row
#pragma unroll
        for (int g = 0; g < 8; g++) {
            int d = dacc[g];
            d += __shfl_xor_sync(0xffffffffu, d, 1);
            d += __shfl_xor_sync(0xffffffffu, d, 2);
            d += __shfl_xor_sync(0xffffffffu, d, 4);
            d += __shfl_xor_sync(0xffffffffu, d, 8);
            if ((ct & 15) == 0) sdeg[g * 10 + (ct >> 4)] = d;
        }
    } else if (wid < 10) {
        // ---------------- MMA warps: K-split ----------------------------------------
        // warps 0-4: kt {0,1}; warps 5-9: kt {2,3}; rows = (wid%5)*16 .. +15
        const int rowBase = (wid % 5) * 16;
        const int kt0 = (wid / 5) * 2;
        const int sub = lid >> 3, rl = lid & 7;
        int s = 0, ph = 0;
        for (int it = 0; it < NUM_ITERS; it++) {
            MBAR_WAIT(mb + 80 + s * 8, ph);                  // A converted (implies B too)
            uint32_t aBase = sbase + s * STAGE_BYTES + RAW_BYTES;
            uint32_t bBase = aBase + A_BYTES;
#pragma unroll
            for (int kk = 0; kk < 2; kk++) {
                const int kt = kt0 + kk;
                uint32_t a0, a1, a2, a3;
                {
                    int row = rowBase + (sub & 1) * 8 + rl;
                    uint32_t off = (uint32_t)(row * 128 + kt * 32 + (sub >> 1) * 16);
                    off ^= (off >> 3) & 0x70;
                    LDMATRIX_X4(a0, a1, a2, a3, aBase + off);
                }
#pragma unroll
                for (int ng = 0; ng < 4; ng++) {
                    uint32_t b0, b1, b2, b3;
                    int nrow = ng * 16 + (sub >> 1) * 8 + rl;
                    uint32_t off = (uint32_t)(nrow * 128 + kt * 32 + (sub & 1) * 16);
                    off ^= (off >> 3) & 0x70;                // SW128 swizzle
                    LDMATRIX_X4(b0, b1, b2, b3, bBase + off);
                    HMMA_16816(acc[ng * 2],     a0, a1, a2, a3, b0, b1);
                    HMMA_16816(acc[ng * 2 + 1], a0, a1, a2, a3, b2, b3);
                }
            }
            if (lid == 0) MBAR_ARRIVE(mb + s * 8);           // stage consumed
            if (++s == STAGES) { s = 0; ph ^= 1; }
        }
    }

    // ---------------- K-split reduction + epilogue ----------------
    __syncthreads();                       // all TMA/conv/MMA work complete

    float* red = (float*)smem;             // reuse stage area: [80][RED_STRIDE]
    const int gg = lid >> 2, tg = lid & 3;

    if (wid >= 5 && wid < 10) {            // upper K-half stores partials
        const int rowBase = (wid - 5) * 16;
        float* r0 = red + (rowBase + gg) * RED_STRIDE + tg * 2;
        float* r1 = red + (rowBase + gg + 8) * RED_STRIDE + tg * 2;
#pragma unroll
        for (int t = 0; t < 8; t++) {
            *(float2*)(r0 + t * 8) = make_float2(acc[t][0], acc[t][1]);
            *(float2*)(r1 + t * 8) = make_float2(acc[t][2], acc[t][3]);
        }
    }
    __syncthreads();

    if (wid < 5) {                         // lower K-half adds, divides, stores
        const int rowBase = wid * 16;
        const int r0 = rowBase + gg, r1 = r0 + 8;
        float inv0 = 1.0f / (float)sdeg[r0];
        float inv1 = 1.0f / (float)sdeg[r1];
        const float* p0 = red + r0 * RED_STRIDE + tg * 2;
        const float* p1 = red + r1 * RED_STRIDE + tg * 2;
        float* o0 = out + (size_t)(row0 + r0) * OUT_DIM + tg * 2;
        float* o1 = out + (size_t)(row0 + r1) * OUT_DIM + tg * 2;
#pragma unroll
        for (int t = 0; t < 8; t++) {
            float2 q0 = *(const float2*)(p0 + t * 8);
            float2 q1 = *(const float2*)(p1 + t * 8);
            *(float2*)(o0 + t * 8) = make_float2((acc[t][0] + q0.x) * inv0,
                                                 (acc[t][1] + q0.y) * inv0);
            *(float2*)(o1 + t * 8) = make_float2((acc[t][2] + q1.x) * inv1,
                                                 (acc[t][3] + q1.y) * inv1);
        }
    }
}

// ---------------- host ----------------
typedef CUresult (*EncodeFn)(CUtensorMap*, CUtensorMapDataType, cuuint32_t, void*,
                             const cuuint64_t*, const cuuint64_t*, const cuuint32_t*,
                             const cuuint32_t*, CUtensorMapInterleave, CUtensorMapSwizzle,
                             CUtensorMapL2promotion, CUtensorMapFloatOOBfill);

static EncodeFn get_encode_fn() {
    void* fp = nullptr;
    cudaDriverEntryPointQueryResult qr;
#if CUDART_VERSION >= 12050
    cudaGetDriverEntryPointByVersion("cuTensorMapEncodeTiled", &fp, 12000,
                                     cudaEnableDefault, &qr);
#else
    cudaGetDriverEntryPoint("cuTensorMapEncodeTiled", &fp, cudaEnableDefault, &qr);
#endif
    return (EncodeFn)fp;
}

extern "C" void kernel_launch(void* const* d_in, const int* in_sizes, int n_in,
                              void* d_out, int out_size) {
    const float* h   = (const float*)d_in[0];
    void*        adj = (void*)d_in[1];           // int32 [10000,10000], values 0/1
    const float* W   = (const float*)d_in[2];
    float*       out = (float*)d_out;

    prep_kernel<<<N_NODES / M_TILE, 256>>>(h, W);

    EncodeFn enc = get_encode_fn();
    void* whtPtr = nullptr;
    cudaGetSymbolAddress(&whtPtr, g_WhT);

    CUtensorMap tmaAdj, tmaB;
    {   // adj: int32 [10000][10000], box [64,80], no swizzle
        cuuint64_t dims[2]    = {N_NODES, N_NODES};
        cuuint64_t strides[1] = {(cuuint64_t)N_NODES * 4};
        cuuint32_t box[2]     = {K_CHUNK, M_TILE};
        cuuint32_t es[2]      = {1, 1};
        enc(&tmaAdj, CU_TENSOR_MAP_DATA_TYPE_UINT32, 2, adj, dims, strides, box, es,
            CU_TENSOR_MAP_INTERLEAVE_NONE, CU_TENSOR_MAP_SWIZZLE_NONE,
            CU_TENSOR_MAP_L2_PROMOTION_L2_128B, CU_TENSOR_MAP_FLOAT_OOB_FILL_NONE);
    }
    {   // WhT: fp16 [64][10000], box [64,64], SW128 (row = 128B)
        cuuint64_t dims[2]    = {N_NODES, OUT_DIM};
        cuuint64_t strides[1] = {(cuuint64_t)N_NODES * 2};
        cuuint32_t box[2]     = {K_CHUNK, OUT_DIM};
        cuuint32_t es[2]      = {1, 1};
        enc(&tmaB, CU_TENSOR_MAP_DATA_TYPE_FLOAT16, 2, whtPtr, dims, strides, box, es,
            CU_TENSOR_MAP_INTERLEAVE_NONE, CU_TENSOR_MAP_SWIZZLE_128B,
            CU_TENSOR_MAP_L2_PROMOTION_L2_128B, CU_TENSOR_MAP_FLOAT_OOB_FILL_NONE);
    }

    cudaFuncSetAttribute(gat_main_kernel, cudaFuncAttributeMaxDynamicSharedMemorySize,
                         SMEM_TOTAL);
    int grid = N_NODES / M_TILE;   // 125: one CTA per SM, single balanced wave
    gat_main_kernel<<<grid, NTHREADS, SMEM_TOTAL>>>(tmaAdj, tmaB, out);

    (void)in_sizes; (void)n_in; (void)out_size;
}

// round 11
// speedup vs baseline: 1.2332x; 1.0026x over previous
#include <cuda_runtime.h>
#include <cuda.h>
#include <cuda_fp16.h>
#include <cstdint>

// ---------------- problem constants ----------------
#define N_NODES 10000
#define IN_DIM  128
#define OUT_DIM 64
#define M_TILE  80                       // 125 CTAs exactly, 1 per SM
#define K_CHUNK 64
#define NUM_ITERS ((N_NODES + K_CHUNK - 1) / K_CHUNK)   // 157
#define STAGES  5
#define NTHREADS 832                     // 20 MMA (4-way K-split) + 5 conv + 1 producer

#define RAW_BYTES (M_TILE * K_CHUNK * 4)      // 20480 int32 adj tile
#define A_BYTES   (M_TILE * K_CHUNK * 2)      // 10240 fp16 SW128 A tile
#define B_BYTES   (OUT_DIM * K_CHUNK * 2)     // 8192  fp16 SW128 B tile
#define STAGE_BYTES (RAW_BYTES + A_BYTES + B_BYTES)   // 38912 (38*1024)
#define SMEM_MAIN (STAGES * STAGE_BYTES)              // 194560
#define SMEM_TOTAL (SMEM_MAIN + 256 + 1024)

#define RED_STRIDE 68                    // padded cols for partial-sum buffers

// ---------------- device scratch (no allocs allowed) ----------------
__device__ __align__(1024) __half g_WhT[OUT_DIM * N_NODES];

// ---------------- PTX helpers (plain sm_103-safe) ----------------
__device__ __forceinline__ uint32_t smem_u32(const void* p) {
    uint32_t a;
    asm("{ .reg .u64 t; cvta.to.shared.u64 t, %1; cvt.u32.u64 %0, t; }" : "=r"(a) : "l"(p));
    return a;
}
#define MBAR_INIT(a,c)  asm volatile("mbarrier.init.shared.b64 [%0], %1;" :: "r"(a), "r"(c) : "memory")
#define MBAR_ARRIVE(a)  asm volatile("mbarrier.arrive.shared.b64 _, [%0];" :: "r"(a) : "memory")
#define MBAR_EXPECT_TX(a,b) asm volatile("mbarrier.arrive.expect_tx.shared.b64 _, [%0], %1;" :: "r"(a), "r"(b) : "memory")

#define MBAR_WAIT(mbar_addr, phase_parity) do {                                \
    uint32_t _mbar = (uint32_t)(mbar_addr);                                    \
    uint32_t _par  = (uint32_t)(phase_parity);                                 \
    uint32_t _done_;                                                           \
    asm volatile("{\n\t.reg .pred p;\n\t"                                      \
        "mbarrier.try_wait.parity.acquire.cta.shared::cta.b64 p, [%1], %2;\n\t"\
        "selp.b32 %0, 1, 0, p;\n\t}"                                           \
        : "=r"(_done_) : "r"(_mbar), "r"(_par) : "memory");                    \
    if (!_done_) {                                                             \
        asm volatile("{\n\t.reg .pred P1;\n\t"                                 \
            "WL_%=:\n\t"                                                       \
            "mbarrier.try_wait.parity.acquire.cta.shared::cta.b64 P1, [%0], %1, 0x989680;\n\t" \
            "@P1 bra.uni WD_%=;\n\t"                                           \
            "bra.uni WL_%=;\n\t"                                               \
            "WD_%=:\n\t}"                                                      \
            :: "r"(_mbar), "r"(_par) : "memory");                              \
    }                                                                          \
} while (0)

#define TMA_LOAD_2D(dst, map, x, y, mbar)                                      \
    asm volatile(                                                              \
        "cp.async.bulk.tensor.2d.shared::cta.global.tile.mbarrier::complete_tx::bytes " \
        "[%0], [%1, {%2, %3}], [%4];"                                          \
        :: "r"((uint32_t)(dst)), "l"(map), "r"((int)(x)), "r"((int)(y)),       \
           "r"((uint32_t)(mbar)) : "memory")

#define LDMATRIX_X4(r0,r1,r2,r3,addr) \
    asm volatile("ldmatrix.sync.aligned.m8n8.x4.shared.b16 {%0,%1,%2,%3}, [%4];" \
        : "=r"(r0),"=r"(r1),"=r"(r2),"=r"(r3) : "r"(addr))

#define HMMA_16816(C, a0,a1,a2,a3, b0,b1) \
    asm volatile("mma.sync.aligned.m16n8k16.row.col.f32.f16.f16.f32 " \
        "{%0,%1,%2,%3}, {%4,%5,%6,%7}, {%8,%9}, {%0,%1,%2,%3};" \
        : "+f"((C)[0]),"+f"((C)[1]),"+f"((C)[2]),"+f"((C)[3]) \
        : "r"(a0),"r"(a1),"r"(a2),"r"(a3),"r"(b0),"r"(b1))

// ---------------- kernel 1: WhT = (h@W)^T in fp16 (80 nodes / block) ----------------
__global__ void __launch_bounds__(256) prep_kernel(
    const float* __restrict__ h, const float* __restrict__ W)
{
    __shared__ float Ws[IN_DIM * OUT_DIM];      // 32KB [k][col]
    __shared__ float hsm[M_TILE * IN_DIM];      // 40KB [node][k]
    const int tid = threadIdx.x;
    const int node0 = blockIdx.x * M_TILE;

    const float4* W4 = (const float4*)W;
    float4* Ws4 = (float4*)Ws;
#pragma unroll
    for (int i = 0; i < 8; i++) Ws4[tid + i * 256] = W4[tid + i * 256];
    const float4* h4 = (const float4*)(h + (size_t)node0 * IN_DIM);
    float4* hs4 = (float4*)hsm;
#pragma unroll
    for (int i = 0; i < 10; i++) hs4[tid + i * 256] = h4[tid + i * 256];
    __syncthreads();

    const int c4 = tid & 15;                    // cols 4*c4 .. 4*c4+3
    const int ng = tid >> 4;                    // nodes ng*5 .. ng*5+4
    float acc[5][4];
#pragma unroll
    for (int n = 0; n < 5; n++)
#pragma unroll
        for (int c = 0; c < 4; c++) acc[n][c] = 0.f;

#pragma unroll 2
    for (int k4 = 0; k4 < 32; k4++) {
        float4 hv[5];
#pragma unroll
        for (int n = 0; n < 5; n++)
            hv[n] = *(const float4*)&hsm[(ng * 5 + n) * IN_DIM + k4 * 4];
#pragma unroll
        for (int kk = 0; kk < 4; kk++) {
            float4 wv = *(const float4*)&Ws[(k4 * 4 + kk) * OUT_DIM + c4 * 4];
#pragma unroll
            for (int n = 0; n < 5; n++) {
                float hx = (&hv[n].x)[kk];
                acc[n][0] += hx * wv.x;
                acc[n][1] += hx * wv.y;
                acc[n][2] += hx * wv.z;
                acc[n][3] += hx * wv.w;
            }
        }
    }
#pragma unroll
    for (int n = 0; n < 5; n++) {
        int node = node0 + ng * 5 + n;
#pragma unroll
        for (int c = 0; c < 4; c++)
            g_WhT[(size_t)(c4 * 4 + c) * N_NODES + node] = __float2half(acc[n][c]);
    }
}

// ---------------- kernel 2: masked mean via 4-way K-split HMMA pipeline ----------------
__global__ void __launch_bounds__(NTHREADS, 1) gat_main_kernel(
    const __grid_constant__ CUtensorMap tma_adj,
    const __grid_constant__ CUtensorMap tma_b,
    float* __restrict__ out)
{
    extern __shared__ char smem_raw[];
    const int tid = threadIdx.x;
    const int wid = tid >> 5;
    const int lid = tid & 31;

    uint32_t sb0 = smem_u32(smem_raw);
    uint32_t sbase = (sb0 + 1023u) & ~1023u;
    char* smem = smem_raw + (sbase - sb0);
    const uint32_t mb = sbase + SMEM_MAIN;
    // mbar layout: empty[5]@0 (cnt 20), full_raw[5]@40 (TMA tx), full_conv[5]@80 (cnt 160)

    __shared__ int sdeg[M_TILE];

    if (tid == 0) {
        for (int s = 0; s < STAGES; s++) {
            MBAR_INIT(mb + s * 8, 20);          // empty: 20 MMA-warp arrivals
            MBAR_INIT(mb + 40 + s * 8, 1);      // full_raw: TMA tx
            MBAR_INIT(mb + 80 + s * 8, 160);    // full_conv: 160 conv threads
        }
    }
    __syncthreads();

    const int row0 = blockIdx.x * M_TILE;
    float acc[8][4];
#pragma unroll
    for (int t = 0; t < 8; t++)
#pragma unroll
        for (int p = 0; p < 4; p++) acc[t][p] = 0.f;

    if (tid == 800) {
        // ---------------- TMA producer ----------------
        int s = 0, ph = 1;
        for (int it = 0; it < NUM_ITERS; it++) {
            MBAR_WAIT(mb + s * 8, ph);                       // wait stage empty
            uint32_t dst = sbase + s * STAGE_BYTES;
            uint32_t fr = mb + 40 + s * 8;
            MBAR_EXPECT_TX(fr, RAW_BYTES + B_BYTES);
            TMA_LOAD_2D(dst, &tma_adj, it * K_CHUNK, row0, fr);
            TMA_LOAD_2D(dst + RAW_BYTES + A_BYTES, &tma_b, it * K_CHUNK, 0, fr);
            if (++s == STAGES) { s = 0; ph ^= 1; }
        }
    } else if (wid >= 20 && wid < 25) {
        // ---------------- converters: int32 adj -> fp16 A (SW128) + degree ----------
        const int ct = tid - 640;                            // 0..159
        int dacc[8];
#pragma unroll
        for (int g = 0; g < 8; g++) dacc[g] = 0;
        int s = 0, ph = 0;
        for (int it = 0; it < NUM_ITERS; it++) {
            MBAR_WAIT(mb + 40 + s * 8, ph);                  // wait TMA data
            const uint4* rawv = (const uint4*)(smem + s * STAGE_BYTES);
            char* aT = smem + s * STAGE_BYTES + RAW_BYTES;
#pragma unroll
            for (int g = 0; g < 8; g++) {
                int idx = g * 160 + ct;                      // linear: conflict-free LDS.128
                uint4 v = rawv[idx];
                dacc[g] += (int)(v.x + v.y + v.z + v.w);
                uint32_t u0 = v.x * 0x3C00u + v.y * 0x3C000000u;  // 2x fp16 {1.0,0.0}
                uint32_t u1 = v.z * 0x3C00u + v.w * 0x3C000000u;
                uint32_t off = (uint32_t)((idx >> 4) * 128 + (idx & 15) * 8);
                off ^= (off >> 3) & 0x70;                    // SW128 swizzle
                *(uint2*)(aT + off) = make_uint2(u0, u1);
            }
            MBAR_ARRIVE(mb + 80 + s * 8);                    // release A tile
            if (++s == STAGES) { s = 0; ph ^= 1; }
        }
        // degree reduce: row = g*10 + (ct>>4); 16 lanes share a row
#pragma unroll
        for (int g = 0; g < 8; g++) {
            int d = dacc[g];
            d += __shfl_xor_sync(0xffffffffu, d, 1);
            d += __shfl_xor_sync(0xffffffffu, d, 2);
            d += __shfl_xor_sync(0xffffffffu, d, 4);
            d += __shfl_xor_sync(0xffffffffu, d, 8);
            if ((ct & 15) == 0) sdeg[g * 10 + (ct >> 4)] = d;
        }
    } else if (wid < 20) {
        // ---------------- MMA warps: 4-way K-split ----------------------------------
        // warp w: rows (w%5)*16..+15, kt = w/5 (one K=16 slab per warp per iter)
        const int rowBase = (wid % 5) * 16;
        const int kt = wid / 5;
        const int sub = lid >> 3, rl = lid & 7;
        int s = 0, ph = 0;
        for (int it = 0; it < NUM_ITERS; it++) {
            MBAR_WAIT(mb + 80 + s * 8, ph);                  // A converted (implies B too)
            uint32_t aBase = sbase + s * STAGE_BYTES + RAW_BYTES;
            uint32_t bBase = aBase + A_BYTES;
            uint32_t a0, a1, a2, a3;
            {
                int row = rowBase + (sub & 1) * 8 + rl;
                uint32_t off = (uint32_t)(row * 128 + kt * 32 + (sub >> 1) * 16);
                off ^= (off >> 3) & 0x70;
                LDMATRIX_X4(a0, a1, a2, a3, aBase + off);
            }
#pragma unroll
            for (int ng = 0; ng < 4; ng++) {
                uint32_t b0, b1, b2, b3;
                int nrow = ng * 16 + (sub >> 1) * 8 + rl;
                uint32_t off = (uint32_t)(nrow * 128 + kt * 32 + (sub & 1) * 16);
                off ^= (off >> 3) & 0x70;                    // SW128 swizzle
                LDMATRIX_X4(b0, b1, b2, b3, bBase + off);
                HMMA_16816(acc[ng * 2],     a0, a1, a2, a3, b0, b1);
                HMMA_16816(acc[ng * 2 + 1], a0, a1, a2, a3, b2, b3);
            }
            if (lid == 0) MBAR_ARRIVE(mb + s * 8);           // stage consumed
            if (++s == STAGES) { s = 0; ph ^= 1; }
        }
    }

    // ---------------- 4-way K reduction + epilogue ----------------
    __syncthreads();                       // all TMA/conv/MMA work complete

    float* red = (float*)smem;             // reuse stage area: 3 x [80][RED_STRIDE]
    const int gg = lid >> 2, tg = lid & 3;

    if (wid >= 5 && wid < 20) {            // kt 1..3 store partials
        const int kt = wid / 5;
        const int rowBase = (wid % 5) * 16;
        float* base = red + (size_t)(kt - 1) * (M_TILE * RED_STRIDE);
        float* r0 = base + (rowBase + gg) * RED_STRIDE + tg * 2;
        float* r1 = base + (rowBase + gg + 8) * RED_STRIDE + tg * 2;
#pragma unroll
        for (int t = 0; t < 8; t++) {
            *(float2*)(r0 + t * 8) = make_float2(acc[t][0], acc[t][1]);
            *(float2*)(r1 + t * 8) = make_float2(acc[t][2], acc[t][3]);
        }
    }
    __syncthreads();

    if (wid < 5) {                         // kt 0 adds all partials, divides, stores
        const int rowBase = wid * 16;
        const int r0 = rowBase + gg, r1 = r0 + 8;
        float inv0 = 1.0f / (float)sdeg[r0];
        float inv1 = 1.0f / (float)sdeg[r1];
        float* o0 = out + (size_t)(row0 + r0) * OUT_DIM + tg * 2;
        float* o1 = out + (size_t)(row0 + r1) * OUT_DIM + tg * 2;
#pragma unroll
        for (int t = 0; t < 8; t++) {
            float s00 = acc[t][0], s01 = acc[t][1];
            float s10 = acc[t][2], s11 = acc[t][3];
#pragma unroll
            for (int k = 0; k < 3; k++) {
                const float* base = red + (size_t)k * (M_TILE * RED_STRIDE);
                float2 q0 = *(const float2*)(base + r0 * RED_STRIDE + tg * 2 + t * 8);
                float2 q1 = *(const float2*)(base + r1 * RED_STRIDE + tg * 2 + t * 8);
                s00 += q0.x; s01 += q0.y;
                s10 += q1.x; s11 += q1.y;
            }
            *(float2*)(o0 + t * 8) = make_float2(s00 * inv0, s01 * inv0);
            *(float2*)(o1 + t * 8) = make_float2(s10 * inv1, s11 * inv1);
        }
    }
}

// ---------------- host ----------------
typedef CUresult (*EncodeFn)(CUtensorMap*, CUtensorMapDataType, cuuint32_t, void*,
                             const cuuint64_t*, const cuuint64_t*, const cuuint32_t*,
                             const cuuint32_t*, CUtensorMapInterleave, CUtensorMapSwizzle,
                             CUtensorMapL2promotion, CUtensorMapFloatOOBfill);

static EncodeFn get_encode_fn() {
    void* fp = nullptr;
    cudaDriverEntryPointQueryResult qr;
#if CUDART_VERSION >= 12050
    cudaGetDriverEntryPointByVersion("cuTensorMapEncodeTiled", &fp, 12000,
                                     cudaEnableDefault, &qr);
#else
    cudaGetDriverEntryPoint("cuTensorMapEncodeTiled", &fp, cudaEnableDefault, &qr);
#endif
    return (EncodeFn)fp;
}

extern "C" void kernel_launch(void* const* d_in, const int* in_sizes, int n_in,
                              void* d_out, int out_size) {
    const float* h   = (const float*)d_in[0];
    void*        adj = (void*)d_in[1];           // int32 [10000,10000], values 0/1
    const float* W   = (const float*)d_in[2];
    float*       out = (float*)d_out;

    prep_kernel<<<N_NODES / M_TILE, 256>>>(h, W);

    EncodeFn enc = get_encode_fn();
    void* whtPtr = nullptr;
    cudaGetSymbolAddress(&whtPtr, g_WhT);

    CUtensorMap tmaAdj, tmaB;
    {   // adj: int32 [10000][10000], box [64,80], no swizzle
        cuuint64_t dims[2]    = {N_NODES, N_NODES};
        cuuint64_t strides[1] = {(cuuint64_t)N_NODES * 4};
        cuuint32_t box[2]     = {K_CHUNK, M_TILE};
        cuuint32_t es[2]      = {1, 1};
        enc(&tmaAdj, CU_TENSOR_MAP_DATA_TYPE_UINT32, 2, adj, dims, strides, box, es,
            CU_TENSOR_MAP_INTERLEAVE_NONE, CU_TENSOR_MAP_SWIZZLE_NONE,
            CU_TENSOR_MAP_L2_PROMOTION_L2_128B, CU_TENSOR_MAP_FLOAT_OOB_FILL_NONE);
    }
    {   // WhT: fp16 [64][10000], box [64,64], SW128 (row = 128B)
        cuuint64_t dims[2]    = {N_NODES, OUT_DIM};
        cuuint64_t strides[1] = {(cuuint64_t)N_NODES * 2};
        cuuint32_t box[2]     = {K_CHUNK, OUT_DIM};
        cuuint32_t es[2]      = {1, 1};
        enc(&tmaB, CU_TENSOR_MAP_DATA_TYPE_FLOAT16, 2, whtPtr, dims, strides, box, es,
            CU_TENSOR_MAP_INTERLEAVE_NONE, CU_TENSOR_MAP_SWIZZLE_128B,
            CU_TENSOR_MAP_L2_PROMOTION_L2_128B, CU_TENSOR_MAP_FLOAT_OOB_FILL_NONE);
    }

    cudaFuncSetAttribute(gat_main_kernel, cudaFuncAttributeMaxDynamicSharedMemorySize,
                         SMEM_TOTAL);
    int grid = N_NODES / M_TILE;   // 125: one CTA per SM, single balanced wave
    gat_main_kernel<<<grid, NTHREADS, SMEM_TOTAL>>>(tmaAdj, tmaB, out);

    (void)in_sizes; (void)n_in; (void)out_size;
}

// round 14
// speedup vs baseline: 1.3429x; 1.0890x over previous
#include <cuda_runtime.h>
#include <cuda.h>
#include <cuda_fp16.h>
#include <cstdint>

// ---------------- problem constants ----------------
#define N_NODES 10000
#define IN_DIM  128
#define OUT_DIM 64
#define M_TILE  80                       // 125 CTAs exactly, 1 per SM
#define K_CHUNK 64
#define NUM_ITERS ((N_NODES + K_CHUNK - 1) / K_CHUNK)   // 157
#define STAGES  5
#define NTHREADS 576                     // 12 MMA ({2,2,1}m x 4kt) + 5 conv + 1 producer

#define RAW_BYTES (M_TILE * K_CHUNK * 4)      // 20480 int32 adj tile
#define A_BYTES   (M_TILE * K_CHUNK * 2)      // 10240 fp16 SW128 A tile
#define B_BYTES   (OUT_DIM * K_CHUNK * 2)     // 8192  fp16 SW128 B tile
#define STAGE_BYTES (RAW_BYTES + A_BYTES + B_BYTES)   // 38912 (38*1024)
#define SMEM_MAIN (STAGES * STAGE_BYTES)              // 194560
#define SMEM_TOTAL (SMEM_MAIN + 256 + 1024)

#define RED_STRIDE 68                    // padded cols for partial-sum buffers

// ---------------- device scratch (no allocs allowed) ----------------
__device__ __align__(1024) __half g_WhT[OUT_DIM * N_NODES];

// ---------------- PTX helpers (plain sm_103-safe) ----------------
__device__ __forceinline__ uint32_t smem_u32(const void* p) {
    uint32_t a;
    asm("{ .reg .u64 t; cvta.to.shared.u64 t, %1; cvt.u32.u64 %0, t; }" : "=r"(a) : "l"(p));
    return a;
}
#define MBAR_INIT(a,c)  asm volatile("mbarrier.init.shared.b64 [%0], %1;" :: "r"(a), "r"(c) : "memory")
#define MBAR_ARRIVE(a)  asm volatile("mbarrier.arrive.shared.b64 _, [%0];" :: "r"(a) : "memory")
#define MBAR_EXPECT_TX(a,b) asm volatile("mbarrier.arrive.expect_tx.shared.b64 _, [%0], %1;" :: "r"(a), "r"(b) : "memory")

#define MBAR_WAIT(mbar_addr, phase_parity) do {                                \
    uint32_t _mbar = (uint32_t)(mbar_addr);                                    \
    uint32_t _par  = (uint32_t)(phase_parity);                                 \
    uint32_t _done_;                                                           \
    asm volatile("{\n\t.reg .pred p;\n\t"                                      \
        "mbarrier.try_wait.parity.acquire.cta.shared::cta.b64 p, [%1], %2;\n\t"\
        "selp.b32 %0, 1, 0, p;\n\t}"                                           \
        : "=r"(_done_) : "r"(_mbar), "r"(_par) : "memory");                    \
    if (!_done_) {                                                             \
        asm volatile("{\n\t.reg .pred P1;\n\t"                                 \
            "WL_%=:\n\t"                                                       \
            "mbarrier.try_wait.parity.acquire.cta.shared::cta.b64 P1, [%0], %1, 0x989680;\n\t" \
            "@P1 bra.uni WD_%=;\n\t"                                           \
            "bra.uni WL_%=;\n\t"                                               \
            "WD_%=:\n\t}"                                                      \
            :: "r"(_mbar), "r"(_par) : "memory");                              \
    }                                                                          \
} while (0)

#define TMA_LOAD_2D(dst, map, x, y, mbar)                                      \
    asm volatile(                                                              \
        "cp.async.bulk.tensor.2d.shared::cta.global.tile.mbarrier::complete_tx::bytes " \
        "[%0], [%1, {%2, %3}], [%4];"                                          \
        :: "r"((uint32_t)(dst)), "l"(map), "r"((int)(x)), "r"((int)(y)),       \
           "r"((uint32_t)(mbar)) : "memory")

#define LDMATRIX_X4(r0,r1,r2,r3,addr) \
    asm volatile("ldmatrix.sync.aligned.m8n8.x4.shared.b16 {%0,%1,%2,%3}, [%4];" \
        : "=r"(r0),"=r"(r1),"=r"(r2),"=r"(r3) : "r"(addr))

#define HMMA_16816(C, a0,a1,a2,a3, b0,b1) \
    asm volatile("mma.sync.aligned.m16n8k16.row.col.f32.f16.f16.f32 " \
        "{%0,%1,%2,%3}, {%4,%5,%6,%7}, {%8,%9}, {%0,%1,%2,%3};" \
        : "+f"((C)[0]),"+f"((C)[1]),"+f"((C)[2]),"+f"((C)[3]) \
        : "r"(a0),"r"(a1),"r"(a2),"r"(a3),"r"(b0),"r"(b1))

// ---------------- kernel 1: WhT = (h@W)^T in fp16 (80 nodes / block) ----------------
__global__ void __launch_bounds__(256) prep_kernel(
    const float* __restrict__ h, const float* __restrict__ W)
{
    __shared__ float Ws[IN_DIM * OUT_DIM];      // 32KB [k][col]
    __shared__ float hsm[M_TILE * IN_DIM];      // 40KB [node][k]
    const int tid = threadIdx.x;
    const int node0 = blockIdx.x * M_TILE;

    const float4* W4 = (const float4*)W;
    float4* Ws4 = (float4*)Ws;
#pragma unroll
    for (int i = 0; i < 8; i++) Ws4[tid + i * 256] = W4[tid + i * 256];
    const float4* h4 = (const float4*)(h + (size_t)node0 * IN_DIM);
    float4* hs4 = (float4*)hsm;
#pragma unroll
    for (int i = 0; i < 10; i++) hs4[tid + i * 256] = h4[tid + i * 256];
    __syncthreads();

    const int c4 = tid & 15;                    // cols 4*c4 .. 4*c4+3
    const int ng = tid >> 4;                    // nodes ng*5 .. ng*5+4
    float acc[5][4];
#pragma unroll
    for (int n = 0; n < 5; n++)
#pragma unroll
        for (int c = 0; c < 4; c++) acc[n][c] = 0.f;

#pragma unroll 2
    for (int k4 = 0; k4 < 32; k4++) {
        float4 hv[5];
#pragma unroll
        for (int n = 0; n < 5; n++)
            hv[n] = *(const float4*)&hsm[(ng * 5 + n) * IN_DIM + k4 * 4];
#pragma unroll
        for (int kk = 0; kk < 4; kk++) {
            float4 wv = *(const float4*)&Ws[(k4 * 4 + kk) * OUT_DIM + c4 * 4];
#pragma unroll
            for (int n = 0; n < 5; n++) {
                float hx = (&hv[n].x)[kk];
                acc[n][0] += hx * wv.x;
                acc[n][1] += hx * wv.y;
                acc[n][2] += hx * wv.z;
                acc[n][3] += hx * wv.w;
            }
        }
    }
#pragma unroll
    for (int n = 0; n < 5; n++) {
        int node = node0 + ng * 5 + n;
#pragma unroll
        for (int c = 0; c < 4; c++)
            g_WhT[(size_t)(c4 * 4 + c) * N_NODES + node] = __float2half(acc[n][c]);
    }
}

// ---------------- kernel 2: masked mean; {2,2,1}m x 4kt HMMA pipeline ----------------
__global__ void __launch_bounds__(NTHREADS, 1) gat_main_kernel(
    const __grid_constant__ CUtensorMap tma_adj,
    const __grid_constant__ CUtensorMap tma_b,
    float* __restrict__ out)
{
    extern __shared__ char smem_raw[];
    const int tid = threadIdx.x;
    const int wid = tid >> 5;
    const int lid = tid & 31;

    uint32_t sb0 = smem_u32(smem_raw);
    uint32_t sbase = (sb0 + 1023u) & ~1023u;
    char* smem = smem_raw + (sbase - sb0);
    const uint32_t mb = sbase + SMEM_MAIN;
    // mbar layout: empty[5]@0 (cnt 12), full_raw[5]@40 (TMA tx), full_conv[5]@80 (cnt 160)

    __shared__ int sdeg[M_TILE];

    if (tid == 0) {
        for (int s = 0; s < STAGES; s++) {
            MBAR_INIT(mb + s * 8, 12);          // empty: 12 MMA-warp arrivals
            MBAR_INIT(mb + 40 + s * 8, 1);      // full_raw: TMA tx
            MBAR_INIT(mb + 80 + s * 8, 160);    // full_conv: 160 conv threads
        }
    }
    __syncthreads();

    const int row0 = blockIdx.x * M_TILE;
    float acc[2][8][4];
#pragma unroll
    for (int m = 0; m < 2; m++)
#pragma unroll
        for (int t = 0; t < 8; t++)
#pragma unroll
            for (int p = 0; p < 4; p++) acc[m][t][p] = 0.f;

    if (tid == 544) {
        // ---------------- TMA producer ----------------
        int s = 0, ph = 1;
        for (int it = 0; it < NUM_ITERS; it++) {
            MBAR_WAIT(mb + s * 8, ph);                       // wait stage empty
            uint32_t dst = sbase + s * STAGE_BYTES;
            uint32_t fr = mb + 40 + s * 8;
            MBAR_EXPECT_TX(fr, RAW_BYTES + B_BYTES);
            TMA_LOAD_2D(dst, &tma_adj, it * K_CHUNK, row0, fr);
            TMA_LOAD_2D(dst + RAW_BYTES + A_BYTES, &tma_b, it * K_CHUNK, 0, fr);
            if (++s == STAGES) { s = 0; ph ^= 1; }
        }
    } else if (wid >= 12 && wid < 17) {
        // ---------------- converters: int32 adj -> fp16 A (SW128) + degree ----------
        const int ct = tid - 384;                            // 0..159
        int dacc[8];
#pragma unroll
        for (int g = 0; g < 8; g++) dacc[g] = 0;
        int s = 0, ph = 0;
        for (int it = 0; it < NUM_ITERS; it++) {
            MBAR_WAIT(mb + 40 + s * 8, ph);                  // wait TMA data
            const uint4* rawv = (const uint4*)(smem + s * STAGE_BYTES);
            char* aT = smem + s * STAGE_BYTES + RAW_BYTES;
#pragma unroll
            for (int g = 0; g < 8; g++) {
                int idx = g * 160 + ct;                      // linear: conflict-free LDS.128
                uint4 v = rawv[idx];
                dacc[g] += (int)(v.x + v.y + v.z + v.w);
                uint32_t u0 = v.x * 0x3C00u + v.y * 0x3C000000u;  // 2x fp16 {1.0,0.0}
                uint32_t u1 = v.z * 0x3C00u + v.w * 0x3C000000u;
                uint32_t off = (uint32_t)((idx >> 4) * 128 + (idx & 15) * 8);
                off ^= (off >> 3) & 0x70;                    // SW128 swizzle
                *(uint2*)(aT + off) = make_uint2(u0, u1);
            }
            MBAR_ARRIVE(mb + 80 + s * 8);                    // release A tile
            if (++s == STAGES) { s = 0; ph ^= 1; }
        }
        // degree reduce: row = g*10 + (ct>>4); 16 lanes share a row
#pragma unroll
        for (int g = 0; g < 8; g++) {
            int d = dacc[g];
            d += __shfl_xor_sync(0xffffffffu, d, 1);
            d += __shfl_xor_sync(0xffffffffu, d, 2);
            d += __shfl_xor_sync(0xffffffffu, d, 4);
            d += __shfl_xor_sync(0xffffffffu, d, 8);
            if ((ct & 15) == 0) sdeg[g * 10 + (ct >> 4)] = d;
        }
    } else if (wid < 12) {
        // ---------------- MMA warps: {2,2,1} row-units x 4-way K-split ---------------
        // warp w: rg = w%3 (rg 0,1 -> 2 m-tiles, rg 2 -> 1), kt = w/3
        const int rg = wid % 3;
        const int kt = wid / 3;
        const int mcnt = (rg == 2) ? 1 : 2;
        const int mbase = rg * 32;
        const int sub = lid >> 3, rl = lid & 7;
        int s = 0, ph = 0;
        for (int it = 0; it < NUM_ITERS; it++) {
            MBAR_WAIT(mb + 80 + s * 8, ph);                  // A converted (implies B too)
            uint32_t aBase = sbase + s * STAGE_BYTES + RAW_BYTES;
            uint32_t bBase = aBase + A_BYTES;
            uint32_t a[2][4];
#pragma unroll
            for (int mt = 0; mt < 2; mt++) {
                if (mt < mcnt) {
                    int row = mbase + mt * 16 + (sub & 1) * 8 + rl;
                    uint32_t off = (uint32_t)(row * 128 + kt * 32 + (sub >> 1) * 16);
                    off ^= (off >> 3) & 0x70;
                    LDMATRIX_X4(a[mt][0], a[mt][1], a[mt][2], a[mt][3], aBase + off);
                }
            }
#pragma unroll
            for (int ng = 0; ng < 4; ng++) {
                uint32_t b0, b1, b2, b3;
                int nrow = ng * 16 + (sub >> 1) * 8 + rl;
                uint32_t off = (uint32_t)(nrow * 128 + kt * 32 + (sub & 1) * 16);
                off ^= (off >> 3) & 0x70;                    // SW128 swizzle
                LDMATRIX_X4(b0, b1, b2, b3, bBase + off);
                HMMA_16816(acc[0][ng * 2],     a[0][0], a[0][1], a[0][2], a[0][3], b0, b1);
                HMMA_16816(acc[0][ng * 2 + 1], a[0][0], a[0][1], a[0][2], a[0][3], b2, b3);
                if (mcnt == 2) {
                    HMMA_16816(acc[1][ng * 2],     a[1][0], a[1][1], a[1][2], a[1][3], b0, b1);
                    HMMA_16816(acc[1][ng * 2 + 1], a[1][0], a[1][1], a[1][2], a[1][3], b2, b3);
                }
            }
            if (lid == 0) MBAR_ARRIVE(mb + s * 8);           // stage consumed
            if (++s == STAGES) { s = 0; ph ^= 1; }
        }
    }

    // ---------------- 4-way K reduction + epilogue ----------------
    __syncthreads();                       // all TMA/conv/MMA work complete

    float* red = (float*)smem;             // reuse stage area: 3 x [80][RED_STRIDE]
    const int gg = lid >> 2, tg = lid & 3;

    if (wid >= 3 && wid < 12) {            // kt 1..3 store partials
        const int rg = wid % 3;
        const int kt = wid / 3;
        const int mcnt = (rg == 2) ? 1 : 2;
        float* base = red + (size_t)(kt - 1) * (M_TILE * RED_STRIDE);
#pragma unroll
        for (int mt = 0; mt < 2; mt++) {
            if (mt < mcnt) {
                const int r0 = rg * 32 + mt * 16 + gg, r1 = r0 + 8;
                float* p0 = base + r0 * RED_STRIDE + tg * 2;
                float* p1 = base + r1 * RED_STRIDE + tg * 2;
#pragma unroll
                for (int t = 0; t < 8; t++) {
                    *(float2*)(p0 + t * 8) = make_float2(acc[mt][t][0], acc[mt][t][1]);
                    *(float2*)(p1 + t * 8) = make_float2(acc[mt][t][2], acc[mt][t][3]);
                }
            }
        }
    }
    __syncthreads();

    if (wid < 3) {                         // kt 0 adds all partials, divides, stores
        const int rg = wid;
        const int mcnt = (rg == 2) ? 1 : 2;
#pragma unroll
        for (int mt = 0; mt < 2; mt++) {
            if (mt < mcnt) {
                const int r0 = rg * 32 + mt * 16 + gg, r1 = r0 + 8;
                float inv0 = 1.0f / (float)sdeg[r0];
                float inv1 = 1.0f / (float)sdeg[r1];
                float* o0 = out + (size_t)(row0 + r0) * OUT_DIM + tg * 2;
                float* o1 = out + (size_t)(row0 + r1) * OUT_DIM + tg * 2;
#pragma unroll
                for (int t = 0; t < 8; t++) {
                    float s00 = acc[mt][t][0], s01 = acc[mt][t][1];
                    float s10 = acc[mt][t][2], s11 = acc[mt][t][3];
#pragma unroll
                    for (int k = 0; k < 3; k++) {
                        const float* base = red + (size_t)k * (M_TILE * RED_STRIDE);
                        float2 q0 = *(const float2*)(base + r0 * RED_STRIDE + tg * 2 + t * 8);
                        float2 q1 = *(const float2*)(base + r1 * RED_STRIDE + tg * 2 + t * 8);
                        s00 += q0.x; s01 += q0.y;
                        s10 += q1.x; s11 += q1.y;
                    }
                    *(float2*)(o0 + t * 8) = make_float2(s00 * inv0, s01 * inv0);
                    *(float2*)(o1 + t * 8) = make_float2(s10 * inv1, s11 * inv1);
                }
            }
        }
    }
}

// ---------------- host ----------------
typedef CUresult (*EncodeFn)(CUtensorMap*, CUtensorMapDataType, cuuint32_t, void*,
                             const cuuint64_t*, const cuuint64_t*, const cuuint32_t*,
                             const cuuint32_t*, CUtensorMapInterleave, CUtensorMapSwizzle,
                             CUtensorMapL2promotion, CUtensorMapFloatOOBfill);

static EncodeFn get_encode_fn() {
    void* fp = nullptr;
    cudaDriverEntryPointQueryResult qr;
#if CUDART_VERSION >= 12050
    cudaGetDriverEntryPointByVersion("cuTensorMapEncodeTiled", &fp, 12000,
                                     cudaEnableDefault, &qr);
#else
    cudaGetDriverEntryPoint("cuTensorMapEncodeTiled", &fp, cudaEnableDefault, &qr);
#endif
    return (EncodeFn)fp;
}

extern "C" void kernel_launch(void* const* d_in, const int* in_sizes, int n_in,
                              void* d_out, int out_size) {
    const float* h   = (const float*)d_in[0];
    void*        adj = (void*)d_in[1];           // int32 [10000,10000], values 0/1
    const float* W   = (const float*)d_in[2];
    float*       out = (float*)d_out;

    prep_kernel<<<N_NODES / M_TILE, 256>>>(h, W);

    EncodeFn enc = get_encode_fn();
    void* whtPtr = nullptr;
    cudaGetSymbolAddress(&whtPtr, g_WhT);

    CUtensorMap tmaAdj, tmaB;
    {   // adj: int32 [10000][10000], box [64,80], no swizzle
        cuuint64_t dims[2]    = {N_NODES, N_NODES};
        cuuint64_t strides[1] = {(cuuint64_t)N_NODES * 4};
        cuuint32_t box[2]     = {K_CHUNK, M_TILE};
        cuuint32_t es[2]      = {1, 1};
        enc(&tmaAdj, CU_TENSOR_MAP_DATA_TYPE_UINT32, 2, adj, dims, strides, box, es,
            CU_TENSOR_MAP_INTERLEAVE_NONE, CU_TENSOR_MAP_SWIZZLE_NONE,
            CU_TENSOR_MAP_L2_PROMOTION_L2_128B, CU_TENSOR_MAP_FLOAT_OOB_FILL_NONE);
    }
    {   // WhT: fp16 [64][10000], box [64,64], SW128 (row = 128B)
        cuuint64_t dims[2]    = {N_NODES, OUT_DIM};
        cuuint64_t strides[1] = {(cuuint64_t)N_NODES * 2};
        cuuint32_t box[2]     = {K_CHUNK, OUT_DIM};
        cuuint32_t es[2]      = {1, 1};
        enc(&tmaB, CU_TENSOR_MAP_DATA_TYPE_FLOAT16, 2, whtPtr, dims, strides, box, es,
            CU_TENSOR_MAP_INTERLEAVE_NONE, CU_TENSOR_MAP_SWIZZLE_128B,
            CU_TENSOR_MAP_L2_PROMOTION_L2_128B, CU_TENSOR_MAP_FLOAT_OOB_FILL_NONE);
    }

    cudaFuncSetAttribute(gat_main_kernel, cudaFuncAttributeMaxDynamicSharedMemorySize,
                         SMEM_TOTAL);
    int grid = N_NODES / M_TILE;   // 125: one CTA per SM, single balanced wave
    gat_main_kernel<<<grid, NTHREADS, SMEM_TOTAL>>>(tmaAdj, tmaB, out);

    (void)in_sizes; (void)n_in; (void)out_size;
}